// round 14
// baseline (speedup 1.0000x reference)
#include <cuda_runtime.h>
#include <math.h>

#define H_IN   192
#define W_IN   192
#define HOUT   96
#define WOUT   96
#define C1     32
#define NN     17
#define BATCH  128

// Block: 32x16 output px = 16x8 Winograd tiles; 256 threads
// Thread = (adjacent-x tile pair, g); g = tid>>6 is warp-uniform.
#define NTHR   256
#define BX     32
#define BY     16
#define NTX    16
#define NTY    8
#define NTILE  (NTX*NTY)   // 128
#define BLOCKS_PER_B 18    // (96/32)*(96/16)

// h tile: 18 x 34, stride 36
#define HROWS  18
#define HCOLS  34
#define HSTR2  36
#define SMH    (HROWS*HSTR2)      // 648 floats per channel

// input tile: 37 x 69, stride 72
#define ITSY   37
#define ITSX   69
#define ISTR   72
#define NPOS   (HROWS*HCOLS)      // 612
#define NP1    3                  // ceil(612/256)

#define SM_W1T (C1*12)            // 384
#define SM_IN  (ITSY*ISTR)        // 2664
#define SM_H   (C1*SMH)           // 20736
#define SM_U   (4*C1*NN*4)        // 8704  ([g][c][n][4])
#define SM_FLOATS (SM_W1T + SM_IN + SM_H + SM_U)
#define SM_BYTES  ((SM_FLOATS + 40) * 4)

__constant__ float cB1[C1];
__constant__ float cB2[NN];

typedef unsigned long long ull;

__device__ float g_cms[(size_t)BATCH*NN*HOUT*WOUT];
__device__ ull   g_peak[BATCH*NN];   // zero-init; reset by last block each call
__device__ int   g_cnt[BATCH];       // zero-init; reset by last block each call

// monotonic (value desc, first-index) ordering key
static __device__ __forceinline__ ull pkkey(float v, unsigned idx) {
    unsigned k = __float_as_uint(v);
    k = (k & 0x80000000u) ? ~k : (k | 0x80000000u);
    return ((ull)k << 32) | (0xFFFFFFFFu - idx);
}

// ---------- output chunk emitter + warp-reduced argmax ----------
template<int NB, int CH>
static __device__ __forceinline__ void emit_chunk(
    const float (&MA)[NN][4], const float (&MB)[NN][4],
    float* M_s, ull* s_red, int tA, int tB, int g, int tid,
    int b, int x0, int y0)
{
    #pragma unroll
    for (int nl = 0; nl < CH; nl++) {
        const int n = NB + nl;
        *(float4*)(M_s + (tA*CH + nl)*20 + 4*g) =
            make_float4(MA[n][0], MA[n][1], MA[n][2], MA[n][3]);
        *(float4*)(M_s + (tB*CH + nl)*20 + 4*g) =
            make_float4(MB[n][0], MB[n][1], MB[n][2], MB[n][3]);
    }
    __syncthreads();

    // NTILE*CH is a multiple of 32 (1152 or 1024): warps are never partial,
    // so the shfl reduction below is safe.
    for (int i = tid; i < NTILE*CH; i += NTHR) {
        const int t2 = i & (NTILE-1);
        const int nl = i >> 7;           // warp-uniform within an iteration
        const int n  = NB + nl;
        const float* mp = M_s + (t2*CH + nl)*20;
        const float4 m0 = *(const float4*)(mp);
        const float4 m1 = *(const float4*)(mp + 4);
        const float4 m2 = *(const float4*)(mp + 8);
        const float4 m3 = *(const float4*)(mp + 12);

        // Z = A^T M ; Y = Z A
        const float z00 = m0.x + m1.x + m2.x;
        const float z01 = m0.y + m1.y + m2.y;
        const float z02 = m0.z + m1.z + m2.z;
        const float z03 = m0.w + m1.w + m2.w;
        const float z10 = m1.x - m2.x - m3.x;
        const float z11 = m1.y - m2.y - m3.y;
        const float z12 = m1.z - m2.z - m3.z;
        const float z13 = m1.w - m2.w - m3.w;
        const float bb = cB2[n];
        const float y00 = z00 + z01 + z02 + bb;
        const float y01 = z01 - z02 - z03 + bb;
        const float y10 = z10 + z11 + z12 + bb;
        const float y11 = z11 - z12 - z13 + bb;

        const int ty_t = t2 >> 4, tx_t = t2 & 15;
        const int gy = y0 + 2*ty_t, gx = x0 + 2*tx_t;
        float* o = g_cms + ((size_t)(b*NN + n)*HOUT + gy)*WOUT + gx;
        *(float2*)o          = make_float2(y00, y01);
        *(float2*)(o + WOUT) = make_float2(y10, y11);

        // fused argmax: pack 4 px, warp-reduce, 1 atomic per warp
        const unsigned base = (unsigned)(gy*WOUT + gx);
        ull m = pkkey(y00, base);
        ull tk = pkkey(y01, base + 1);      if (tk > m) m = tk;
        tk = pkkey(y10, base + WOUT);       if (tk > m) m = tk;
        tk = pkkey(y11, base + WOUT + 1);   if (tk > m) m = tk;
        #pragma unroll
        for (int s = 16; s; s >>= 1) {
            ull o2 = __shfl_xor_sync(0xffffffffu, m, s);
            if (o2 > m) m = o2;
        }
        if ((tid & 31) == 0) atomicMax(&s_red[n], m);
    }
    __syncthreads();
}

__global__ __launch_bounds__(NTHR, 1)
void conv_winograd_kernel(const float* __restrict__ crops,
                          const float* __restrict__ W1g,
                          const float* __restrict__ W2g,
                          float* __restrict__ out)
{
    extern __shared__ float sm[];
    float* s_w1t = sm;                 // [C1][12]
    float* s_in  = sm + SM_W1T;        // [ITSY][ISTR]
    float* s_h   = s_in + SM_IN;       // [C1][HROWS][HSTR2]
    float* s_U   = s_h + SM_H;         // [g][C1][NN][4]
    ull*   s_red = (ull*)(s_U + SM_U); // [NN]

    const int tid = threadIdx.x;
    const int x0  = blockIdx.x * BX;
    const int y0  = blockIdx.y * BY;
    const int b   = blockIdx.z;

    if (tid < NN) s_red[tid] = 0ULL;

    // ---- stage transposed W1 ----
    for (int i = tid; i < 9*C1; i += NTHR) {
        int k = i / C1, c = i - k*C1;
        s_w1t[c*12 + k] = W1g[i];
    }
    // ---- stage input tile ----
    const float* img = crops + (size_t)b * H_IN * W_IN;
    for (int i = tid; i < ITSY*ITSX; i += NTHR) {
        int r  = i / ITSX, cc = i - r*ITSX;
        int iy = 2*y0 - 2 + r;
        int ix = 2*x0 - 2 + cc;
        float v = 0.f;
        if (iy >= 0 && iy < H_IN && ix >= 0 && ix < W_IN) v = img[iy*W_IN + ix];
        s_in[r*ISTR + cc] = v;
    }
    // ---- precompute U = G w G^T, layout [g][c][n][4] ----
    for (int i = tid; i < C1*NN; i += NTHR) {
        const int c = i / NN, n = i - c*NN;
        float gr[3][3];
        #pragma unroll
        for (int r = 0; r < 3; r++)
            #pragma unroll
            for (int s = 0; s < 3; s++)
                gr[r][s] = W2g[((r*3 + s)*C1 + c)*NN + n];
        float T[4][3];
        #pragma unroll
        for (int s = 0; s < 3; s++) {
            const float t02 = gr[0][s] + gr[2][s];
            T[0][s] = gr[0][s];
            T[1][s] = 0.5f*(t02 + gr[1][s]);
            T[2][s] = 0.5f*(t02 - gr[1][s]);
            T[3][s] = gr[2][s];
        }
        #pragma unroll
        for (int r = 0; r < 4; r++) {
            const float u02 = T[r][0] + T[r][2];
            *(float4*)(s_U + ((r*C1 + c)*NN + n)*4) = make_float4(
                T[r][0], 0.5f*(u02 + T[r][1]), 0.5f*(u02 - T[r][1]), T[r][2]);
        }
    }
    __syncthreads();

    // ---- conv1: all 32 channels -> s_h (zero outside [0,96)) ----
    float in9[NP1][9];
    int   offh[NP1];
    bool  pmask[NP1], pborder[NP1];
    #pragma unroll
    for (int i = 0; i < NP1; i++) {
        const int p = tid + i*NTHR;
        pmask[i] = (p < NPOS);
        const int pp = pmask[i] ? p : 0;
        const int ly = pp / HCOLS - 1;
        const int lx = pp - (pp / HCOLS)*HCOLS - 1;
        offh[i] = (ly+1)*HSTR2 + (lx+1);
        const int gy = y0 + ly, gx = x0 + lx;
        pborder[i] = (gy >= 0) & (gy < HOUT) & (gx >= 0) & (gx < WOUT);
        const float* r0 = s_in + (2*ly + 2)*ISTR + (2*lx + 2);
        #pragma unroll
        for (int ky = 0; ky < 3; ky++) {
            const float2 v2 = *(const float2*)(r0 + ky*ISTR);
            in9[i][ky*3+0] = v2.x;
            in9[i][ky*3+1] = v2.y;
            in9[i][ky*3+2] = r0[ky*ISTR + 2];
        }
    }
    #pragma unroll 1
    for (int c = 0; c < C1; c++) {
        const float4 wa = *(const float4*)(s_w1t + c*12);
        const float4 wb = *(const float4*)(s_w1t + c*12 + 4);
        const float  w8 = s_w1t[c*12 + 8];
        const float  b1c = cB1[c];
        float* hc = s_h + c*SMH;
        #pragma unroll
        for (int i = 0; i < NP1; i++) {
            if (!pmask[i]) continue;
            float a = b1c;
            a = fmaf(in9[i][0], wa.x, a);
            a = fmaf(in9[i][1], wa.y, a);
            a = fmaf(in9[i][2], wa.z, a);
            a = fmaf(in9[i][3], wa.w, a);
            a = fmaf(in9[i][4], wb.x, a);
            a = fmaf(in9[i][5], wb.y, a);
            a = fmaf(in9[i][6], wb.z, a);
            a = fmaf(in9[i][7], wb.w, a);
            a = fmaf(in9[i][8], w8,   a);
            a = fmaxf(a, 0.f);
            hc[offh[i]] = pborder[i] ? a : 0.f;
        }
    }
    __syncthreads();

    // ---- conv2 Winograd: thread = (x-adjacent tile pair, g); g warp-uniform ----
    const int g   = tid >> 6;          // 0..3, uniform per warp pair
    const int q   = tid & 63;
    const int txp = q & 7;             // tile-pair x index (covers tiles 2*txp, 2*txp+1)
    const int ty_t = q >> 3;           // tile y
    const int tA  = ty_t*NTX + 2*txp;
    const int tB  = tA + 1;

    int rA, rB; float sgn;
    if      (g == 0) { rA = 0; rB = 2; sgn = -1.f; }
    else if (g == 1) { rA = 1; rB = 2; sgn =  1.f; }
    else if (g == 2) { rA = 2; rB = 1; sgn = -1.f; }
    else             { rA = 1; rB = 3; sgn = -1.f; }
    const int rowA = (2*ty_t + rA)*HSTR2 + 4*txp;
    const int rowB = (2*ty_t + rB)*HSTR2 + 4*txp;
    const float4* ug = (const float4*)(s_U + g*C1*NN*4);

    float MA[NN][4], MB[NN][4];
    #pragma unroll
    for (int n = 0; n < NN; n++) {
        MA[n][0]=0.f; MA[n][1]=0.f; MA[n][2]=0.f; MA[n][3]=0.f;
        MB[n][0]=0.f; MB[n][1]=0.f; MB[n][2]=0.f; MB[n][3]=0.f;
    }

    #pragma unroll 1
    for (int c = 0; c < C1; c++) {
        const float* hc = s_h + c*SMH;
        const float4 a4 = *(const float4*)(hc + rowA);       // 16B aligned
        const float2 a2 = *(const float2*)(hc + rowA + 4);
        const float4 b4 = *(const float4*)(hc + rowB);
        const float2 b2 = *(const float2*)(hc + rowB + 4);

        const float W0 = fmaf(sgn, b4.x, a4.x);
        const float W1 = fmaf(sgn, b4.y, a4.y);
        const float W2 = fmaf(sgn, b4.z, a4.z);
        const float W3 = fmaf(sgn, b4.w, a4.w);
        const float W4 = fmaf(sgn, b2.x, a2.x);
        const float W5 = fmaf(sgn, b2.y, a2.y);

        const float VA0 = W0 - W2, VA1 = W1 + W2, VA2 = W2 - W1, VA3 = W1 - W3;
        const float VB0 = W2 - W4, VB1 = W3 + W4, VB2 = W4 - W3, VB3 = W3 - W5;

        const float4* up = ug + c*NN;      // broadcast loads, amortized over 2 tiles
        #pragma unroll
        for (int n = 0; n < NN; n++) {
            const float4 u = up[n];
            MA[n][0] = fmaf(u.x, VA0, MA[n][0]);
            MA[n][1] = fmaf(u.y, VA1, MA[n][1]);
            MA[n][2] = fmaf(u.z, VA2, MA[n][2]);
            MA[n][3] = fmaf(u.w, VA3, MA[n][3]);
            MB[n][0] = fmaf(u.x, VB0, MB[n][0]);
            MB[n][1] = fmaf(u.y, VB1, MB[n][1]);
            MB[n][2] = fmaf(u.z, VB2, MB[n][2]);
            MB[n][3] = fmaf(u.w, VB3, MB[n][3]);
        }
    }
    __syncthreads();

    // ---- output transform + fused argmax, 2 static n-chunks ----
    float* M_s = s_h;
    emit_chunk<0, 9>(MA, MB, M_s, s_red, tA, tB, g, tid, b, x0, y0);
    emit_chunk<9, 8>(MA, MB, M_s, s_red, tA, tB, g, tid, b, x0, y0);

    // ---- publish per-block argmax, last block refines ----
    if (tid < NN) atomicMax(&g_peak[b*NN + tid], s_red[tid]);
    __threadfence();
    __syncthreads();

    __shared__ int s_last;
    if (tid == 0) {
        int prev = atomicAdd(&g_cnt[b], 1);
        s_last = (prev == BLOCKS_PER_B - 1) ? 1 : 0;
    }
    __syncthreads();

    if (s_last) {
        __threadfence();
        if (tid < NN) {
            const int bn = b*NN + tid;
            ull p = g_peak[bn];
            unsigned idx = 0xFFFFFFFFu - (unsigned)(p & 0xFFFFFFFFu);
            int yi = idx / WOUT;
            int xi = idx - yi*WOUT;
            const float* cm = g_cms + (size_t)bn * HOUT * WOUT;
            float val = cm[idx];

            int xm = max(xi-1, 0), xp = min(xi+1, WOUT-1);
            int ym = max(yi-1, 0), yp = min(yi+1, HOUT-1);
            float ddx = cm[yi*WOUT + xp] - cm[yi*WOUT + xm];
            float ddy = cm[yp*WOUT + xi] - cm[ym*WOUT + xi];
            float sx = (ddx > 0.f) ? 1.f : ((ddx < 0.f) ? -1.f : 0.f);
            float sy = (ddy > 0.f) ? 1.f : ((ddy < 0.f) ? -1.f : 0.f);

            float px = ((float)xi + 0.25f*sx) * 2.0f;
            float py = ((float)yi + 0.25f*sy) * 2.0f;
            if (!(val >= 0.2f)) { px = nanf(""); py = nanf(""); }

            out[bn*3 + 0] = px;
            out[bn*3 + 1] = py;
            out[bn*3 + 2] = val;

            g_peak[bn] = 0ULL;            // reset for next replay
        }
        __syncthreads();
        if (tid == 0) g_cnt[b] = 0;       // reset for next replay
    }
}

extern "C" void kernel_launch(void* const* d_in, const int* in_sizes, int n_in,
                              void* d_out, int out_size)
{
    const float* crops = (const float*)d_in[0];
    const float* W1    = (const float*)d_in[1];
    const float* b1    = (const float*)d_in[2];
    const float* W2    = (const float*)d_in[3];
    const float* b2    = (const float*)d_in[4];
    float* out = (float*)d_out;

    cudaMemcpyToSymbolAsync(cB1, b1, C1*sizeof(float), 0, cudaMemcpyDeviceToDevice, 0);
    cudaMemcpyToSymbolAsync(cB2, b2, NN*sizeof(float), 0, cudaMemcpyDeviceToDevice, 0);

    cudaFuncSetAttribute(conv_winograd_kernel,
                         cudaFuncAttributeMaxDynamicSharedMemorySize, SM_BYTES);

    dim3 grid(WOUT/BX, HOUT/BY, BATCH);   // 3 x 6 x 128
    conv_winograd_kernel<<<grid, NTHR, SM_BYTES>>>(crops, W1, W2, out);
}

// round 15
// speedup vs baseline: 1.1153x; 1.1153x over previous
#include <cuda_runtime.h>
#include <math.h>

#define H_IN   192
#define W_IN   192
#define HOUT   96
#define WOUT   96
#define C1     32
#define NN     17
#define BATCH  128

// Block: 32x16 output px = 16x8 Winograd tiles; 512 threads.
// Thread = (x-adjacent tile pair, g, n-half); tid>>6 = (nh,g) warp-uniform.
#define NTHR   512
#define BX     32
#define BY     16
#define NTX    16
#define NTY    8
#define NTILE  (NTX*NTY)   // 128
#define BLOCKS_PER_B 18    // (96/32)*(96/16)
#define NND    18          // node dim padded 17 -> 18 (n=17 zeroed)

// h tile: 18 x 34, stride 36
#define HROWS  18
#define HCOLS  34
#define HSTR2  36
#define SMH    (HROWS*HSTR2)      // 648 floats per channel

// input tile: 37 x 69, stride 72
#define ITSY   37
#define ITSX   69
#define ISTR   72
#define NPOS   (HROWS*HCOLS)      // 612
#define NP1    2                  // ceil(612/512)

#define SM_W1T (C1*12)            // 384
#define SM_IN  (ITSY*ISTR)        // 2664
#define SM_H   (C1*SMH)           // 20736
#define SM_U   (4*C1*NND*4)       // 9216  ([g][c][18][4])
#define SM_FLOATS (SM_W1T + SM_IN + SM_H + SM_U)
#define SM_BYTES  ((SM_FLOATS + 40) * 4)   // ~132.3 KB
// M staging reuses s_h+s_U (29952 floats); max chunk = 128*9*20 = 23040 ok

__constant__ float cB1[C1];
__constant__ float cB2[NN];

typedef unsigned long long ull;

__device__ float g_cms[(size_t)BATCH*NN*HOUT*WOUT];
__device__ ull   g_peak[BATCH*NN];   // zero-init; reset by last block each call
__device__ int   g_cnt[BATCH];       // zero-init; reset by last block each call

// monotonic (value desc, first-index) ordering key
static __device__ __forceinline__ ull pkkey(float v, unsigned idx) {
    unsigned k = __float_as_uint(v);
    k = (k & 0x80000000u) ? ~k : (k | 0x80000000u);
    return ((ull)k << 32) | (0xFFFFFFFFu - idx);
}

// ---------- output chunk emitter + warp-reduced argmax ----------
// Chunk NB..NB+CH-1 is staged by threads whose nh == (NB!=0); accumulator
// local index nl aligns with global n = NB+nl for those threads.
template<int NB, int CH>
static __device__ __forceinline__ void emit_chunk(
    const float (&MA)[9][4], const float (&MB)[9][4],
    float* M_s, ull* s_red, int tA, int tB, int g, int nh, int tid,
    int b, int x0, int y0)
{
    if (nh == (NB != 0 ? 1 : 0)) {
        #pragma unroll
        for (int nl = 0; nl < CH; nl++) {
            *(float4*)(M_s + (tA*CH + nl)*20 + 4*g) =
                make_float4(MA[nl][0], MA[nl][1], MA[nl][2], MA[nl][3]);
            *(float4*)(M_s + (tB*CH + nl)*20 + 4*g) =
                make_float4(MB[nl][0], MB[nl][1], MB[nl][2], MB[nl][3]);
        }
    }
    __syncthreads();

    // NTILE*CH = 1152 or 1024; active thread sets are whole warps,
    // so full-mask shfl is safe.
    for (int i = tid; i < NTILE*CH; i += NTHR) {
        const int t2 = i & (NTILE-1);
        const int nl = i >> 7;
        const int n  = NB + nl;
        const float* mp = M_s + (t2*CH + nl)*20;
        const float4 m0 = *(const float4*)(mp);
        const float4 m1 = *(const float4*)(mp + 4);
        const float4 m2 = *(const float4*)(mp + 8);
        const float4 m3 = *(const float4*)(mp + 12);

        // Z = A^T M ; Y = Z A
        const float z00 = m0.x + m1.x + m2.x;
        const float z01 = m0.y + m1.y + m2.y;
        const float z02 = m0.z + m1.z + m2.z;
        const float z03 = m0.w + m1.w + m2.w;
        const float z10 = m1.x - m2.x - m3.x;
        const float z11 = m1.y - m2.y - m3.y;
        const float z12 = m1.z - m2.z - m3.z;
        const float z13 = m1.w - m2.w - m3.w;
        const float bb = cB2[n];
        const float y00 = z00 + z01 + z02 + bb;
        const float y01 = z01 - z02 - z03 + bb;
        const float y10 = z10 + z11 + z12 + bb;
        const float y11 = z11 - z12 - z13 + bb;

        const int ty_t = t2 >> 4, tx_t = t2 & 15;
        const int gy = y0 + 2*ty_t, gx = x0 + 2*tx_t;
        float* o = g_cms + ((size_t)(b*NN + n)*HOUT + gy)*WOUT + gx;
        *(float2*)o          = make_float2(y00, y01);
        *(float2*)(o + WOUT) = make_float2(y10, y11);

        // fused argmax: pack 4 px, warp-reduce, 1 atomic per warp
        const unsigned base = (unsigned)(gy*WOUT + gx);
        ull m = pkkey(y00, base);
        ull tk = pkkey(y01, base + 1);      if (tk > m) m = tk;
        tk = pkkey(y10, base + WOUT);       if (tk > m) m = tk;
        tk = pkkey(y11, base + WOUT + 1);   if (tk > m) m = tk;
        #pragma unroll
        for (int s = 16; s; s >>= 1) {
            ull o2 = __shfl_xor_sync(0xffffffffu, m, s);
            if (o2 > m) m = o2;
        }
        if ((tid & 31) == 0) atomicMax(&s_red[n], m);
    }
    __syncthreads();
}

__global__ __launch_bounds__(NTHR, 1)
void conv_winograd_kernel(const float* __restrict__ crops,
                          const float* __restrict__ W1g,
                          const float* __restrict__ W2g,
                          float* __restrict__ out)
{
    extern __shared__ float sm[];
    float* s_w1t = sm;                 // [C1][12]
    float* s_in  = sm + SM_W1T;        // [ITSY][ISTR]
    float* s_h   = s_in + SM_IN;       // [C1][HROWS][HSTR2]
    float* s_U   = s_h + SM_H;         // [g][C1][NND][4]
    ull*   s_red = (ull*)(s_U + SM_U); // [NN]

    const int tid = threadIdx.x;
    const int x0  = blockIdx.x * BX;
    const int y0  = blockIdx.y * BY;
    const int b   = blockIdx.z;

    if (tid < NN) s_red[tid] = 0ULL;

    // ---- stage transposed W1 ----
    for (int i = tid; i < 9*C1; i += NTHR) {
        int k = i / C1, c = i - k*C1;
        s_w1t[c*12 + k] = W1g[i];
    }
    // ---- stage input tile ----
    const float* img = crops + (size_t)b * H_IN * W_IN;
    for (int i = tid; i < ITSY*ITSX; i += NTHR) {
        int r  = i / ITSX, cc = i - r*ITSX;
        int iy = 2*y0 - 2 + r;
        int ix = 2*x0 - 2 + cc;
        float v = 0.f;
        if (iy >= 0 && iy < H_IN && ix >= 0 && ix < W_IN) v = img[iy*W_IN + ix];
        s_in[r*ISTR + cc] = v;
    }
    // ---- precompute U = G w G^T, layout [g][c][NND][4]; n=17 zeroed ----
    for (int i = tid; i < C1*NN; i += NTHR) {
        const int c = i / NN, n = i - c*NN;
        float gr[3][3];
        #pragma unroll
        for (int r = 0; r < 3; r++)
            #pragma unroll
            for (int s = 0; s < 3; s++)
                gr[r][s] = W2g[((r*3 + s)*C1 + c)*NN + n];
        float T[4][3];
        #pragma unroll
        for (int s = 0; s < 3; s++) {
            const float t02 = gr[0][s] + gr[2][s];
            T[0][s] = gr[0][s];
            T[1][s] = 0.5f*(t02 + gr[1][s]);
            T[2][s] = 0.5f*(t02 - gr[1][s]);
            T[3][s] = gr[2][s];
        }
        #pragma unroll
        for (int r = 0; r < 4; r++) {
            const float u02 = T[r][0] + T[r][2];
            *(float4*)(s_U + ((r*C1 + c)*NND + n)*4) = make_float4(
                T[r][0], 0.5f*(u02 + T[r][1]), 0.5f*(u02 - T[r][1]), T[r][2]);
        }
    }
    for (int i = tid; i < 4*C1; i += NTHR)   // zero pad node 17
        *(float4*)(s_U + (i*NND + 17)*4) = make_float4(0.f, 0.f, 0.f, 0.f);
    __syncthreads();

    // ---- conv1: all 32 channels -> s_h (zero outside [0,96)) ----
    float in9[NP1][9];
    int   offh[NP1];
    bool  pmask[NP1], pborder[NP1];
    #pragma unroll
    for (int i = 0; i < NP1; i++) {
        const int p = tid + i*NTHR;
        pmask[i] = (p < NPOS);
        const int pp = pmask[i] ? p : 0;
        const int ly = pp / HCOLS - 1;
        const int lx = pp - (pp / HCOLS)*HCOLS - 1;
        offh[i] = (ly+1)*HSTR2 + (lx+1);
        const int gy = y0 + ly, gx = x0 + lx;
        pborder[i] = (gy >= 0) & (gy < HOUT) & (gx >= 0) & (gx < WOUT);
        const float* r0 = s_in + (2*ly + 2)*ISTR + (2*lx + 2);
        #pragma unroll
        for (int ky = 0; ky < 3; ky++) {
            const float2 v2 = *(const float2*)(r0 + ky*ISTR);
            in9[i][ky*3+0] = v2.x;
            in9[i][ky*3+1] = v2.y;
            in9[i][ky*3+2] = r0[ky*ISTR + 2];
        }
    }
    #pragma unroll 1
    for (int c = 0; c < C1; c++) {
        const float4 wa = *(const float4*)(s_w1t + c*12);
        const float4 wb = *(const float4*)(s_w1t + c*12 + 4);
        const float  w8 = s_w1t[c*12 + 8];
        const float  b1c = cB1[c];
        float* hc = s_h + c*SMH;
        #pragma unroll
        for (int i = 0; i < NP1; i++) {
            if (!pmask[i]) continue;
            float a = b1c;
            a = fmaf(in9[i][0], wa.x, a);
            a = fmaf(in9[i][1], wa.y, a);
            a = fmaf(in9[i][2], wa.z, a);
            a = fmaf(in9[i][3], wa.w, a);
            a = fmaf(in9[i][4], wb.x, a);
            a = fmaf(in9[i][5], wb.y, a);
            a = fmaf(in9[i][6], wb.z, a);
            a = fmaf(in9[i][7], wb.w, a);
            a = fmaf(in9[i][8], w8,   a);
            a = fmaxf(a, 0.f);
            hc[offh[i]] = pborder[i] ? a : 0.f;
        }
    }
    __syncthreads();

    // ---- conv2 Winograd: thread = (x tile-pair, g, n-half) ----
    const int gi  = tid >> 6;          // (nh,g) warp-uniform
    const int g   = gi & 3;
    const int nh  = gi >> 2;           // 0: nodes 0-8, 1: nodes 9-16(+pad)
    const int nbase = nh * 9;
    const int q   = tid & 63;
    const int txp = q & 7;
    const int ty_t = q >> 3;
    const int tA  = ty_t*NTX + 2*txp;
    const int tB  = tA + 1;

    int rA, rB; float sgn;
    if      (g == 0) { rA = 0; rB = 2; sgn = -1.f; }
    else if (g == 1) { rA = 1; rB = 2; sgn =  1.f; }
    else if (g == 2) { rA = 2; rB = 1; sgn = -1.f; }
    else             { rA = 1; rB = 3; sgn = -1.f; }
    const int rowA = (2*ty_t + rA)*HSTR2 + 4*txp;
    const int rowB = (2*ty_t + rB)*HSTR2 + 4*txp;
    const float4* ug = ((const float4*)s_U) + (size_t)g*C1*NND + nbase;

    float MA[9][4], MB[9][4];
    #pragma unroll
    for (int n = 0; n < 9; n++) {
        MA[n][0]=0.f; MA[n][1]=0.f; MA[n][2]=0.f; MA[n][3]=0.f;
        MB[n][0]=0.f; MB[n][1]=0.f; MB[n][2]=0.f; MB[n][3]=0.f;
    }

    #pragma unroll 1
    for (int c = 0; c < C1; c++) {
        const float* hc = s_h + c*SMH;
        const float4 a4 = *(const float4*)(hc + rowA);
        const float2 a2 = *(const float2*)(hc + rowA + 4);
        const float4 b4 = *(const float4*)(hc + rowB);
        const float2 b2 = *(const float2*)(hc + rowB + 4);

        const float W0 = fmaf(sgn, b4.x, a4.x);
        const float W1 = fmaf(sgn, b4.y, a4.y);
        const float W2 = fmaf(sgn, b4.z, a4.z);
        const float W3 = fmaf(sgn, b4.w, a4.w);
        const float W4 = fmaf(sgn, b2.x, a2.x);
        const float W5 = fmaf(sgn, b2.y, a2.y);

        const float VA0 = W0 - W2, VA1 = W1 + W2, VA2 = W2 - W1, VA3 = W1 - W3;
        const float VB0 = W2 - W4, VB1 = W3 + W4, VB2 = W4 - W3, VB3 = W3 - W5;

        const float4* up = ug + c*NND;     // broadcast, shared by 2 tiles
        #pragma unroll
        for (int n = 0; n < 9; n++) {      // n=8@nh=1 hits zero pad (harmless)
            const float4 u = up[n];
            MA[n][0] = fmaf(u.x, VA0, MA[n][0]);
            MA[n][1] = fmaf(u.y, VA1, MA[n][1]);
            MA[n][2] = fmaf(u.z, VA2, MA[n][2]);
            MA[n][3] = fmaf(u.w, VA3, MA[n][3]);
            MB[n][0] = fmaf(u.x, VB0, MB[n][0]);
            MB[n][1] = fmaf(u.y, VB1, MB[n][1]);
            MB[n][2] = fmaf(u.z, VB2, MB[n][2]);
            MB[n][3] = fmaf(u.w, VB3, MB[n][3]);
        }
    }
    __syncthreads();

    // ---- output transform + fused argmax, 2 n-chunks ----
    float* M_s = s_h;
    emit_chunk<0, 9>(MA, MB, M_s, s_red, tA, tB, g, nh, tid, b, x0, y0);
    emit_chunk<9, 8>(MA, MB, M_s, s_red, tA, tB, g, nh, tid, b, x0, y0);

    // ---- publish per-block argmax, last block refines ----
    if (tid < NN) atomicMax(&g_peak[b*NN + tid], s_red[tid]);
    __threadfence();
    __syncthreads();

    __shared__ int s_last;
    if (tid == 0) {
        int prev = atomicAdd(&g_cnt[b], 1);
        s_last = (prev == BLOCKS_PER_B - 1) ? 1 : 0;
    }
    __syncthreads();

    if (s_last) {
        __threadfence();
        if (tid < NN) {
            const int bn = b*NN + tid;
            ull p = g_peak[bn];
            unsigned idx = 0xFFFFFFFFu - (unsigned)(p & 0xFFFFFFFFu);
            int yi = idx / WOUT;
            int xi = idx - yi*WOUT;
            const float* cm = g_cms + (size_t)bn * HOUT * WOUT;
            float val = cm[idx];

            int xm = max(xi-1, 0), xp = min(xi+1, WOUT-1);
            int ym = max(yi-1, 0), yp = min(yi+1, HOUT-1);
            float ddx = cm[yi*WOUT + xp] - cm[yi*WOUT + xm];
            float ddy = cm[yp*WOUT + xi] - cm[ym*WOUT + xi];
            float sx = (ddx > 0.f) ? 1.f : ((ddx < 0.f) ? -1.f : 0.f);
            float sy = (ddy > 0.f) ? 1.f : ((ddy < 0.f) ? -1.f : 0.f);

            float px = ((float)xi + 0.25f*sx) * 2.0f;
            float py = ((float)yi + 0.25f*sy) * 2.0f;
            if (!(val >= 0.2f)) { px = nanf(""); py = nanf(""); }

            out[bn*3 + 0] = px;
            out[bn*3 + 1] = py;
            out[bn*3 + 2] = val;

            g_peak[bn] = 0ULL;            // reset for next replay
        }
        __syncthreads();
        if (tid == 0) g_cnt[b] = 0;       // reset for next replay
    }
}

extern "C" void kernel_launch(void* const* d_in, const int* in_sizes, int n_in,
                              void* d_out, int out_size)
{
    const float* crops = (const float*)d_in[0];
    const float* W1    = (const float*)d_in[1];
    const float* b1    = (const float*)d_in[2];
    const float* W2    = (const float*)d_in[3];
    const float* b2    = (const float*)d_in[4];
    float* out = (float*)d_out;

    cudaMemcpyToSymbolAsync(cB1, b1, C1*sizeof(float), 0, cudaMemcpyDeviceToDevice, 0);
    cudaMemcpyToSymbolAsync(cB2, b2, NN*sizeof(float), 0, cudaMemcpyDeviceToDevice, 0);

    cudaFuncSetAttribute(conv_winograd_kernel,
                         cudaFuncAttributeMaxDynamicSharedMemorySize, SM_BYTES);

    dim3 grid(WOUT/BX, HOUT/BY, BATCH);   // 3 x 6 x 128
    conv_winograd_kernel<<<grid, NTHR, SM_BYTES>>>(crops, W1, W2, out);
}